// round 5
// baseline (speedup 1.0000x reference)
#include <cuda_runtime.h>
#include <cuda_bf16.h>
#include <cstdint>
#include <math.h>

// problem constants
#define BB 8
#define SS 4096
#define DD 1024
#define HH 16
#define HD 64
#define FF 128
#define MM (BB * SS)      // 32768
#define N3 (3 * DD)       // 3072

// ---------------- scratch (device globals; runtime alloc forbidden) ----------------
__device__ __align__(256) float g_wqkv[(size_t)DD * N3];           // packed [1024 x 3072]
__device__ __align__(256) float g_bqkv[N3];
__device__ __align__(256) float g_qkv[(size_t)MM * N3];            // q|k|v cols: t*1024+h*64+e
__device__ __align__(256) float g_part[(size_t)8 * 128 * HD * HD]; // split-K score partials
__device__ __align__(256) float g_w[(size_t)128 * HD * HD];        // softmax weights [bh][k][q]
__device__ __align__(256) float g_attn[(size_t)MM * DD];           // attn out, later reused as h2
__device__ __align__(256) float g_h[(size_t)MM * DD];              // h (rmsnorm'd in place)
__device__ __align__(256) float g_t[(size_t)MM * FF];              // tanh hidden

// ---------------- tf32 helpers ----------------
__device__ __forceinline__ uint32_t f2tf(float x) {
    uint32_t r;
    asm("cvt.rna.tf32.f32 %0, %1;" : "=r"(r) : "f"(x));
    return r;
}
__device__ __forceinline__ void mma8(float* c, const uint32_t* a, const uint32_t* b) {
    asm("mma.sync.aligned.m16n8k8.row.col.f32.tf32.tf32.f32 "
        "{%0,%1,%2,%3}, {%4,%5,%6,%7}, {%8,%9}, {%0,%1,%2,%3};"
        : "+f"(c[0]), "+f"(c[1]), "+f"(c[2]), "+f"(c[3])
        : "r"(a[0]), "r"(a[1]), "r"(a[2]), "r"(a[3]), "r"(b[0]), "r"(b[1]));
}

// ---------------- pack Wq/Wk/Wv (H,D,HD) -> row-major [D, 3072]; pack biases ----------------
__global__ void pack_qkv_kernel(const float* __restrict__ Wq, const float* __restrict__ Wk,
                                const float* __restrict__ Wv, const float* __restrict__ bq,
                                const float* __restrict__ bk, const float* __restrict__ bv) {
    size_t idx = (size_t)blockIdx.x * 256 + threadIdx.x;
    if (idx >= (size_t)DD * N3) return;
    int d = (int)(idx / N3), c = (int)(idx % N3);
    int t = c >> 10, hc = c & 1023;
    const float* W = (t == 0) ? Wq : ((t == 1) ? Wk : Wv);
    g_wqkv[idx] = W[(((size_t)(hc >> 6)) * DD + d) * HD + (hc & 63)];
    if (idx < (size_t)N3) {
        const float* bb2 = (t == 0) ? bq : ((t == 1) ? bk : bv);
        g_bqkv[idx] = bb2[hc];
    }
}

// ---------------- tf32 GEMM: C = A(MxK) @ B(KxN) + bias [+res] [tanh] ----------------
// EPI 0: +bias   EPI 1: +bias+res   EPI 2: tanh(.+bias)
// BM=128 BN=64 BK=16, 256 threads (8 warps as 4x2), warp tile 32x32.
// Double-buffered smem, ONE barrier per k-tile:
//   store(i)->smem[i&1]; sync; prefetch(i+1)->regs; compute from smem[i&1].
// Race-free: a thread reaching store(i+1) has passed sync(i), which implies all
// threads finished compute(i-1) (the last readers of buffer (i+1)&1).
template <int EPI>
__global__ __launch_bounds__(256) void gemm_tf32(
    const float* __restrict__ A, int lda, const float* __restrict__ Bw, int ldb,
    const float* __restrict__ bias, const float* __restrict__ res, int ldr,
    float* __restrict__ C, int ldc, int K) {
    __shared__ __align__(16) uint32_t As[2][128][20];  // pad 4
    __shared__ __align__(16) uint32_t Bs[2][16][72];   // pad 8

    const int row0 = blockIdx.y * 128, col0 = blockIdx.x * 64;
    const int tid = threadIdx.x, lane = tid & 31, warp = tid >> 5;
    const int wm = warp >> 1, wn = warp & 1;
    const int g = lane >> 2, tg = lane & 3;

    // per-thread load coordinates
    const int am0 = tid >> 2, ak = (tid & 3) << 2;  // A: rows am0, am0+64
    const int bk = tid >> 4, bn = (tid & 15) << 2;  // B: 1 row

    float acc[2][4][4];
#pragma unroll
    for (int i = 0; i < 2; i++)
#pragma unroll
        for (int j = 0; j < 4; j++)
#pragma unroll
            for (int c = 0; c < 4; c++) acc[i][j][c] = 0.f;

    const float* Ab = A + (size_t)row0 * lda;
    const float* Bb = Bw + col0;

    // prefetch tile 0 into registers
    float4 ra0 = *(const float4*)(Ab + (size_t)am0 * lda + ak);
    float4 ra1 = *(const float4*)(Ab + (size_t)(am0 + 64) * lda + ak);
    float4 rb = *(const float4*)(Bb + (size_t)bk * ldb + bn);

    const int ntiles = K >> 4;
    for (int it = 0; it < ntiles; it++) {
        const int buf = it & 1;
        // store prefetched tile (rna tf32 conversion at smem-store time)
        As[buf][am0][ak + 0] = f2tf(ra0.x); As[buf][am0][ak + 1] = f2tf(ra0.y);
        As[buf][am0][ak + 2] = f2tf(ra0.z); As[buf][am0][ak + 3] = f2tf(ra0.w);
        As[buf][am0 + 64][ak + 0] = f2tf(ra1.x); As[buf][am0 + 64][ak + 1] = f2tf(ra1.y);
        As[buf][am0 + 64][ak + 2] = f2tf(ra1.z); As[buf][am0 + 64][ak + 3] = f2tf(ra1.w);
        Bs[buf][bk][bn + 0] = f2tf(rb.x); Bs[buf][bk][bn + 1] = f2tf(rb.y);
        Bs[buf][bk][bn + 2] = f2tf(rb.z); Bs[buf][bk][bn + 3] = f2tf(rb.w);
        __syncthreads();

        // issue next tile's global loads (overlap latency with compute below)
        if (it + 1 < ntiles) {
            const int kt = (it + 1) << 4;
            ra0 = *(const float4*)(Ab + (size_t)am0 * lda + kt + ak);
            ra1 = *(const float4*)(Ab + (size_t)(am0 + 64) * lda + kt + ak);
            rb = *(const float4*)(Bb + (size_t)(kt + bk) * ldb + bn);
        }

#pragma unroll
        for (int ks = 0; ks < 16; ks += 8) {
            uint32_t af[2][4], bf[4][2];
#pragma unroll
            for (int mf = 0; mf < 2; mf++) {
                int m = wm * 32 + mf * 16 + g;
                af[mf][0] = As[buf][m][ks + tg];
                af[mf][1] = As[buf][m + 8][ks + tg];
                af[mf][2] = As[buf][m][ks + tg + 4];
                af[mf][3] = As[buf][m + 8][ks + tg + 4];
            }
#pragma unroll
            for (int nf = 0; nf < 4; nf++) {
                int n = wn * 32 + nf * 8 + g;
                bf[nf][0] = Bs[buf][ks + tg][n];
                bf[nf][1] = Bs[buf][ks + tg + 4][n];
            }
#pragma unroll
            for (int mf = 0; mf < 2; mf++)
#pragma unroll
                for (int nf = 0; nf < 4; nf++) mma8(acc[mf][nf], af[mf], bf[nf]);
        }
        // no second barrier: next store targets the other buffer
    }
    // epilogue: c0=(g,2tg) c1=(g,2tg+1) c2=(g+8,2tg) c3=(g+8,2tg+1)
#pragma unroll
    for (int mf = 0; mf < 2; mf++) {
#pragma unroll
        for (int ci = 0; ci < 4; ci++) {
            int r = row0 + wm * 32 + mf * 16 + g + ((ci & 2) ? 8 : 0);
#pragma unroll
            for (int nf = 0; nf < 4; nf++) {
                int c = col0 + wn * 32 + nf * 8 + 2 * tg + (ci & 1);
                float v = acc[mf][nf][ci] + bias[c];
                if (EPI == 1) v += res[(size_t)r * ldr + c];
                if (EPI == 2) v = tanhf(v);
                C[(size_t)r * ldc + c] = v;
            }
        }
    }
}

// ---------------- scores partials: P[k][q] = sum_{s in chunk} K[s,k]*Q[s,q] ----------------
// grid (128 bh, 8 split), 256 threads; chunk = 512 s
__global__ __launch_bounds__(256) void scores_kernel() {
    __shared__ __align__(16) float Ks[32][68], Qs[32][68];
    const int bh = blockIdx.x, sp = blockIdx.y;
    const int b = bh >> 4, h = bh & 15;
    const int tid = threadIdx.x;
    const int tk = tid >> 4, tq = tid & 15;
    const size_t rowbase = (size_t)(b * SS + sp * 512) * N3;
    const int qoff = h * 64, koff = 1024 + h * 64;

    float acc[4][4];
#pragma unroll
    for (int i = 0; i < 4; i++)
#pragma unroll
        for (int j = 0; j < 4; j++) acc[i][j] = 0.f;

    for (int st = 0; st < 512; st += 32) {
#pragma unroll
        for (int i = 0; i < 2; i++) {
            int L = tid + i * 256;
            int r = L >> 4, c4 = (L & 15) << 2;
            size_t base = rowbase + (size_t)(st + r) * N3;
            *(float4*)&Ks[r][c4] = *(const float4*)(g_qkv + base + koff + c4);
            *(float4*)&Qs[r][c4] = *(const float4*)(g_qkv + base + qoff + c4);
        }
        __syncthreads();
#pragma unroll
        for (int ss = 0; ss < 32; ss++) {
            float4 kk = *(const float4*)&Ks[ss][tk << 2];
            float4 qq = *(const float4*)&Qs[ss][tq << 2];
            float ka[4] = {kk.x, kk.y, kk.z, kk.w};
            float qa[4] = {qq.x, qq.y, qq.z, qq.w};
#pragma unroll
            for (int i = 0; i < 4; i++)
#pragma unroll
                for (int j = 0; j < 4; j++) acc[i][j] += ka[i] * qa[j];
        }
        __syncthreads();
    }
    float* P = g_part + ((size_t)sp * 128 + bh) * 4096;
#pragma unroll
    for (int i = 0; i < 4; i++)
#pragma unroll
        for (int j = 0; j < 4; j++)
            P[(tk * 4 + i) * 64 + (tq * 4 + j)] = acc[i][j];
}

// ---------------- softmax over k: w[k][q] ----------------
__global__ void softmax_kernel(const int* __restrict__ mask) {
    __shared__ float sc[64][65];
    const int bh = blockIdx.x, q = threadIdx.x;  // 64 threads
    const int b = bh >> 4;
    const int mq = mask[b * 64 + q];
    float mx = -3.4e38f;
    for (int k = 0; k < 64; k++) {
        float a = 0.f;
#pragma unroll
        for (int sp = 0; sp < 8; sp++) a += g_part[((size_t)sp * 128 + bh) * 4096 + k * 64 + q];
        a *= 0.125f;
        if (mq == 0) a = -1e30f;
        sc[k][q] = a;
        mx = fmaxf(mx, a);
    }
    float sum = 0.f;
    for (int k = 0; k < 64; k++) {
        float e = __expf(sc[k][q] - mx);
        sc[k][q] = e;
        sum += e;
    }
    float inv = 1.f / sum;
    for (int k = 0; k < 64; k++) g_w[(size_t)bh * 4096 + k * 64 + q] = sc[k][q] * inv;
}

// ---------------- attn: per (bh, s-tile 64): out[s][q] = sum_k v[s][k]*w[k][q] ----------------
// grid (128 bh, 64 stile), 256 threads
__global__ __launch_bounds__(256) void attn_kernel() {
    __shared__ __align__(16) float ws[64][68];
    __shared__ __align__(16) float vs[64][68];  // stride 68 floats: float4-safe
    const int bh = blockIdx.x, stile = blockIdx.y;
    const int b = bh >> 4, h = bh & 15;
    const int tid = threadIdx.x;
    const int s0 = stile * 64;
    const int vbase = 2048 + h * 64;

    for (int i = tid; i < 4096; i += 256) ws[i >> 6][i & 63] = g_w[(size_t)bh * 4096 + i];
#pragma unroll
    for (int i = 0; i < 4; i++) {
        int L = tid + i * 256;
        int r = L >> 4, c4 = (L & 15) << 2;
        *(float4*)&vs[r][c4] =
            *(const float4*)(g_qkv + (size_t)(b * SS + s0 + r) * N3 + vbase + c4);
    }
    __syncthreads();

    const int ts = tid >> 4, tq = tid & 15;  // 16 s-groups x 16 q-groups
    float acc[4][4];
#pragma unroll
    for (int i = 0; i < 4; i++)
#pragma unroll
        for (int j = 0; j < 4; j++) acc[i][j] = 0.f;
#pragma unroll 8
    for (int k = 0; k < 64; k++) {
        float4 w4 = *(const float4*)&ws[k][tq << 2];
        float wa[4] = {w4.x, w4.y, w4.z, w4.w};
#pragma unroll
        for (int i = 0; i < 4; i++) {
            float v = vs[ts * 4 + i][k];
#pragma unroll
            for (int j = 0; j < 4; j++) acc[i][j] += v * wa[j];
        }
    }
#pragma unroll
    for (int i = 0; i < 4; i++) {
        float4 o = make_float4(acc[i][0], acc[i][1], acc[i][2], acc[i][3]);
        *(float4*)(g_attn + (size_t)(b * SS + s0 + ts * 4 + i) * DD + h * 64 + (tq << 2)) = o;
    }
}

// ---------------- rmsnorm: out[row] = in[row] * rsqrt(mean(in^2)+eps) * g ----------------
__global__ __launch_bounds__(256) void rmsnorm_kernel(const float* __restrict__ in,
                                                      const float* __restrict__ gg,
                                                      float* __restrict__ out) {
    __shared__ float red[8];
    const size_t row = blockIdx.x;
    const int tid = threadIdx.x;
    float4 v = *(const float4*)(in + row * DD + tid * 4);
    float ss = v.x * v.x + v.y * v.y + v.z * v.z + v.w * v.w;
#pragma unroll
    for (int o = 16; o > 0; o >>= 1) ss += __shfl_xor_sync(0xffffffff, ss, o);
    if ((tid & 31) == 0) red[tid >> 5] = ss;
    __syncthreads();
    if (tid < 32) {
        float t = (tid < 8) ? red[tid] : 0.f;
#pragma unroll
        for (int o = 4; o > 0; o >>= 1) t += __shfl_xor_sync(0xffffffff, t, o);
        if (tid == 0) red[0] = t;
    }
    __syncthreads();
    float rs = rsqrtf(red[0] * (1.f / DD) + 1e-6f);
    float4 gv = *(const float4*)(gg + tid * 4);
    float4 o = make_float4(v.x * rs * gv.x, v.y * rs * gv.y, v.z * rs * gv.z, v.w * rs * gv.w);
    *(float4*)(out + row * DD + tid * 4) = o;
}

// ---------------- host ----------------
extern "C" void kernel_launch(void* const* d_in, const int* in_sizes, int n_in,
                              void* d_out, int out_size) {
    const float* x = (const float*)d_in[0];
    const int* amask = (const int*)d_in[1];
    const float* Wq = (const float*)d_in[2];
    const float* bq = (const float*)d_in[3];
    const float* Wk = (const float*)d_in[4];
    const float* bk = (const float*)d_in[5];
    const float* Wv = (const float*)d_in[6];
    const float* bv = (const float*)d_in[7];
    const float* Wo = (const float*)d_in[8];
    const float* bo = (const float*)d_in[9];
    const float* W1 = (const float*)d_in[10];
    const float* b1 = (const float*)d_in[11];
    const float* W2 = (const float*)d_in[12];
    const float* b2 = (const float*)d_in[13];
    const float* g1 = (const float*)d_in[14];
    const float* g2 = (const float*)d_in[15];
    float* out = (float*)d_out;

    float *wqkv, *bqkv, *qkv, *attn, *hbuf, *tbuf;
    cudaGetSymbolAddress((void**)&wqkv, g_wqkv);
    cudaGetSymbolAddress((void**)&bqkv, g_bqkv);
    cudaGetSymbolAddress((void**)&qkv, g_qkv);
    cudaGetSymbolAddress((void**)&attn, g_attn);
    cudaGetSymbolAddress((void**)&hbuf, g_h);
    cudaGetSymbolAddress((void**)&tbuf, g_t);

    // 1. pack weights
    pack_qkv_kernel<<<(DD * N3 + 255) / 256, 256>>>(Wq, Wk, Wv, bq, bk, bv);
    // 2. qkv = x @ Wqkv + b   [32768 x 3072]
    gemm_tf32<0><<<dim3(N3 / 64, MM / 128), 256>>>(x, DD, wqkv, N3, bqkv, nullptr, 0, qkv, N3, DD);
    // 3. score partials + softmax
    scores_kernel<<<dim3(128, 8), 256>>>();
    softmax_kernel<<<128, 64>>>(amask);
    // 4. attn = v @ w
    attn_kernel<<<dim3(128, 64), 256>>>();
    // 5. h = x + attn @ Wo + bo
    gemm_tf32<1><<<dim3(DD / 64, MM / 128), 256>>>(attn, DD, Wo, DD, bo, x, DD, hbuf, DD, DD);
    // 6. h = rmsnorm(h, g1) in place
    rmsnorm_kernel<<<MM, 256>>>(hbuf, g1, hbuf);
    // 7. t = tanh(h @ W1 + b1)
    gemm_tf32<2><<<dim3(FF / 64, MM / 128), 256>>>(hbuf, DD, W1, FF, b1, nullptr, 0, tbuf, FF, DD);
    // 8. h2 = h + t @ W2 + b2   (reuse g_attn)
    gemm_tf32<1><<<dim3(DD / 64, MM / 128), 256>>>(tbuf, FF, W2, DD, b2, hbuf, DD, attn, DD, FF);
    // 9. out = rmsnorm(h2, g2)
    rmsnorm_kernel<<<MM, 256>>>(attn, g2, out);
}

// round 8
// speedup vs baseline: 1.3097x; 1.3097x over previous
#include <cuda_runtime.h>
#include <cuda_bf16.h>
#include <cstdint>
#include <math.h>

// problem constants
#define BB 8
#define SS 4096
#define DD 1024
#define HH 16
#define HD 64
#define FF 128
#define MM (BB * SS)      // 32768
#define N3 (3 * DD)       // 3072

// ---------------- scratch (device globals; runtime alloc forbidden) ----------------
__device__ __align__(256) float g_wqkv[(size_t)DD * N3];           // packed [1024 x 3072]
__device__ __align__(256) float g_bqkv[N3];
__device__ __align__(256) float g_qkv[(size_t)MM * N3];            // q|k|v cols: t*1024+h*64+e
__device__ __align__(256) float g_part[(size_t)8 * 128 * HD * HD]; // split-K score partials
__device__ __align__(256) float g_w[(size_t)128 * HD * HD];        // softmax weights [bh][k][q]
__device__ __align__(256) float g_attn[(size_t)MM * DD];           // attn out, later reused as h2
__device__ __align__(256) float g_h[(size_t)MM * DD];              // h (rmsnorm'd in place)
__device__ __align__(256) float g_t[(size_t)MM * FF];              // tanh hidden

// ---------------- tf32 helpers ----------------
__device__ __forceinline__ uint32_t f2tf(float x) {
    uint32_t r;
    asm("cvt.rna.tf32.f32 %0, %1;" : "=r"(r) : "f"(x));
    return r;
}
__device__ __forceinline__ void mma8(float* c, const uint32_t* a, const uint32_t* b) {
    asm("mma.sync.aligned.m16n8k8.row.col.f32.tf32.tf32.f32 "
        "{%0,%1,%2,%3}, {%4,%5,%6,%7}, {%8,%9}, {%0,%1,%2,%3};"
        : "+f"(c[0]), "+f"(c[1]), "+f"(c[2]), "+f"(c[3])
        : "r"(a[0]), "r"(a[1]), "r"(a[2]), "r"(a[3]), "r"(b[0]), "r"(b[1]));
}

// ---------------- pack Wq/Wk/Wv (H,D,HD) -> row-major [D, 3072]; pack biases ----------------
__global__ void pack_qkv_kernel(const float* __restrict__ Wq, const float* __restrict__ Wk,
                                const float* __restrict__ Wv, const float* __restrict__ bq,
                                const float* __restrict__ bk, const float* __restrict__ bv) {
    size_t idx = (size_t)blockIdx.x * 256 + threadIdx.x;
    if (idx >= (size_t)DD * N3) return;
    int d = (int)(idx / N3), c = (int)(idx % N3);
    int t = c >> 10, hc = c & 1023;
    const float* W = (t == 0) ? Wq : ((t == 1) ? Wk : Wv);
    g_wqkv[idx] = W[(((size_t)(hc >> 6)) * DD + d) * HD + (hc & 63)];
    if (idx < (size_t)N3) {
        const float* bb2 = (t == 0) ? bq : ((t == 1) ? bk : bv);
        g_bqkv[idx] = bb2[hc];
    }
}

// ---------------- tf32 GEMM: C = A(MxK) @ B(KxN) + bias [+res] [tanh] ----------------
// EPI 0: +bias   EPI 1: +bias+res   EPI 2: tanh(.+bias)
// BM=128 BN=128 BK=16, 256 threads (8 warps as 4m x 2n), warp tile 32x64.
// Double-buffered smem, ONE barrier per k-tile; register prefetch of next tile.
template <int EPI>
__global__ __launch_bounds__(256) void gemm_tf32(
    const float* __restrict__ A, int lda, const float* __restrict__ Bw, int ldb,
    const float* __restrict__ bias, const float* __restrict__ res, int ldr,
    float* __restrict__ C, int ldc, int K) {
    __shared__ __align__(16) uint32_t As[2][128][20];   // pad 4: conflict-free frags
    __shared__ __align__(16) uint32_t Bs[2][16][136];   // pad 8: conflict-free frags

    const int row0 = blockIdx.y * 128, col0 = blockIdx.x * 128;
    const int tid = threadIdx.x, lane = tid & 31, warp = tid >> 5;
    const int wm = warp >> 1, wn = warp & 1;
    const int g = lane >> 2, tg = lane & 3;

    // per-thread load coordinates
    const int am0 = tid >> 2, ak = (tid & 3) << 2;  // A: rows am0, am0+64
    const int bk = tid >> 4, bn = (tid & 15) << 2;  // B: cols bn, bn+64

    float acc[2][8][4];
#pragma unroll
    for (int i = 0; i < 2; i++)
#pragma unroll
        for (int j = 0; j < 8; j++)
#pragma unroll
            for (int c = 0; c < 4; c++) acc[i][j][c] = 0.f;

    const float* Ab = A + (size_t)row0 * lda;
    const float* Bb = Bw + col0;

    // prefetch tile 0 into registers
    float4 ra0 = *(const float4*)(Ab + (size_t)am0 * lda + ak);
    float4 ra1 = *(const float4*)(Ab + (size_t)(am0 + 64) * lda + ak);
    float4 rb0 = *(const float4*)(Bb + (size_t)bk * ldb + bn);
    float4 rb1 = *(const float4*)(Bb + (size_t)bk * ldb + bn + 64);

    const int ntiles = K >> 4;
    for (int it = 0; it < ntiles; it++) {
        const int buf = it & 1;
        As[buf][am0][ak + 0] = f2tf(ra0.x); As[buf][am0][ak + 1] = f2tf(ra0.y);
        As[buf][am0][ak + 2] = f2tf(ra0.z); As[buf][am0][ak + 3] = f2tf(ra0.w);
        As[buf][am0 + 64][ak + 0] = f2tf(ra1.x); As[buf][am0 + 64][ak + 1] = f2tf(ra1.y);
        As[buf][am0 + 64][ak + 2] = f2tf(ra1.z); As[buf][am0 + 64][ak + 3] = f2tf(ra1.w);
        Bs[buf][bk][bn + 0] = f2tf(rb0.x); Bs[buf][bk][bn + 1] = f2tf(rb0.y);
        Bs[buf][bk][bn + 2] = f2tf(rb0.z); Bs[buf][bk][bn + 3] = f2tf(rb0.w);
        Bs[buf][bk][bn + 64] = f2tf(rb1.x); Bs[buf][bk][bn + 65] = f2tf(rb1.y);
        Bs[buf][bk][bn + 66] = f2tf(rb1.z); Bs[buf][bk][bn + 67] = f2tf(rb1.w);
        __syncthreads();

        // issue next tile's global loads (overlap with compute below)
        if (it + 1 < ntiles) {
            const int kt = (it + 1) << 4;
            ra0 = *(const float4*)(Ab + (size_t)am0 * lda + kt + ak);
            ra1 = *(const float4*)(Ab + (size_t)(am0 + 64) * lda + kt + ak);
            rb0 = *(const float4*)(Bb + (size_t)(kt + bk) * ldb + bn);
            rb1 = *(const float4*)(Bb + (size_t)(kt + bk) * ldb + bn + 64);
        }

#pragma unroll
        for (int ks = 0; ks < 16; ks += 8) {
            uint32_t af[2][4], bf[8][2];
#pragma unroll
            for (int mf = 0; mf < 2; mf++) {
                int m = wm * 32 + mf * 16 + g;
                af[mf][0] = As[buf][m][ks + tg];
                af[mf][1] = As[buf][m + 8][ks + tg];
                af[mf][2] = As[buf][m][ks + tg + 4];
                af[mf][3] = As[buf][m + 8][ks + tg + 4];
            }
#pragma unroll
            for (int nf = 0; nf < 8; nf++) {
                int n = wn * 64 + nf * 8 + g;
                bf[nf][0] = Bs[buf][ks + tg][n];
                bf[nf][1] = Bs[buf][ks + tg + 4][n];
            }
#pragma unroll
            for (int mf = 0; mf < 2; mf++)
#pragma unroll
                for (int nf = 0; nf < 8; nf++) mma8(acc[mf][nf], af[mf], bf[nf]);
        }
        // no second barrier: next store targets the other buffer
    }
    // epilogue: c0=(g,2tg) c1=(g,2tg+1) c2=(g+8,2tg) c3=(g+8,2tg+1); float2 stores
#pragma unroll
    for (int mf = 0; mf < 2; mf++) {
        const int r0 = row0 + wm * 32 + mf * 16 + g;
#pragma unroll
        for (int nf = 0; nf < 8; nf++) {
            const int c = col0 + wn * 64 + nf * 8 + 2 * tg;
            float b0 = bias[c], b1 = bias[c + 1];
            float v0 = acc[mf][nf][0] + b0, v1 = acc[mf][nf][1] + b1;
            float v2 = acc[mf][nf][2] + b0, v3 = acc[mf][nf][3] + b1;
            if (EPI == 1) {
                float2 r_lo = *(const float2*)(res + (size_t)r0 * ldr + c);
                float2 r_hi = *(const float2*)(res + (size_t)(r0 + 8) * ldr + c);
                v0 += r_lo.x; v1 += r_lo.y; v2 += r_hi.x; v3 += r_hi.y;
            }
            if (EPI == 2) { v0 = tanhf(v0); v1 = tanhf(v1); v2 = tanhf(v2); v3 = tanhf(v3); }
            *(float2*)(C + (size_t)r0 * ldc + c) = make_float2(v0, v1);
            *(float2*)(C + (size_t)(r0 + 8) * ldc + c) = make_float2(v2, v3);
        }
    }
}

// ---------------- scores partials: P[k][q] = sum_{s in chunk} K[s,k]*Q[s,q] ----------------
// grid (128 bh, 8 split), 256 threads; chunk = 512 s
__global__ __launch_bounds__(256) void scores_kernel() {
    __shared__ __align__(16) float Ks[32][68], Qs[32][68];
    const int bh = blockIdx.x, sp = blockIdx.y;
    const int b = bh >> 4, h = bh & 15;
    const int tid = threadIdx.x;
    const int tk = tid >> 4, tq = tid & 15;
    const size_t rowbase = (size_t)(b * SS + sp * 512) * N3;
    const int qoff = h * 64, koff = 1024 + h * 64;

    float acc[4][4];
#pragma unroll
    for (int i = 0; i < 4; i++)
#pragma unroll
        for (int j = 0; j < 4; j++) acc[i][j] = 0.f;

    for (int st = 0; st < 512; st += 32) {
#pragma unroll
        for (int i = 0; i < 2; i++) {
            int L = tid + i * 256;
            int r = L >> 4, c4 = (L & 15) << 2;
            size_t base = rowbase + (size_t)(st + r) * N3;
            *(float4*)&Ks[r][c4] = *(const float4*)(g_qkv + base + koff + c4);
            *(float4*)&Qs[r][c4] = *(const float4*)(g_qkv + base + qoff + c4);
        }
        __syncthreads();
#pragma unroll
        for (int ss = 0; ss < 32; ss++) {
            float4 kk = *(const float4*)&Ks[ss][tk << 2];
            float4 qq = *(const float4*)&Qs[ss][tq << 2];
            float ka[4] = {kk.x, kk.y, kk.z, kk.w};
            float qa[4] = {qq.x, qq.y, qq.z, qq.w};
#pragma unroll
            for (int i = 0; i < 4; i++)
#pragma unroll
                for (int j = 0; j < 4; j++) acc[i][j] += ka[i] * qa[j];
        }
        __syncthreads();
    }
    float* P = g_part + ((size_t)sp * 128 + bh) * 4096;
#pragma unroll
    for (int i = 0; i < 4; i++)
#pragma unroll
        for (int j = 0; j < 4; j++)
            P[(tk * 4 + i) * 64 + (tq * 4 + j)] = acc[i][j];
}

// ---------------- softmax over k: w[k][q] ----------------
__global__ void softmax_kernel(const int* __restrict__ mask) {
    __shared__ float sc[64][65];
    const int bh = blockIdx.x, q = threadIdx.x;  // 64 threads
    const int b = bh >> 4;
    const int mq = mask[b * 64 + q];
    float mx = -3.4e38f;
    for (int k = 0; k < 64; k++) {
        float a = 0.f;
#pragma unroll
        for (int sp = 0; sp < 8; sp++) a += g_part[((size_t)sp * 128 + bh) * 4096 + k * 64 + q];
        a *= 0.125f;
        if (mq == 0) a = -1e30f;
        sc[k][q] = a;
        mx = fmaxf(mx, a);
    }
    float sum = 0.f;
    for (int k = 0; k < 64; k++) {
        float e = __expf(sc[k][q] - mx);
        sc[k][q] = e;
        sum += e;
    }
    float inv = 1.f / sum;
    for (int k = 0; k < 64; k++) g_w[(size_t)bh * 4096 + k * 64 + q] = sc[k][q] * inv;
}

// ---------------- attn: per (bh, s-tile 64): out[s][q] = sum_k v[s][k]*w[k][q] ----------------
// grid (128 bh, 64 stile), 256 threads
__global__ __launch_bounds__(256) void attn_kernel() {
    __shared__ __align__(16) float ws[64][68];
    __shared__ __align__(16) float vs[64][68];  // stride 68 floats: float4-safe
    const int bh = blockIdx.x, stile = blockIdx.y;
    const int b = bh >> 4, h = bh & 15;
    const int tid = threadIdx.x;
    const int s0 = stile * 64;
    const int vbase = 2048 + h * 64;

    for (int i = tid; i < 4096; i += 256) ws[i >> 6][i & 63] = g_w[(size_t)bh * 4096 + i];
#pragma unroll
    for (int i = 0; i < 4; i++) {
        int L = tid + i * 256;
        int r = L >> 4, c4 = (L & 15) << 2;
        *(float4*)&vs[r][c4] =
            *(const float4*)(g_qkv + (size_t)(b * SS + s0 + r) * N3 + vbase + c4);
    }
    __syncthreads();

    const int ts = tid >> 4, tq = tid & 15;  // 16 s-groups x 16 q-groups
    float acc[4][4];
#pragma unroll
    for (int i = 0; i < 4; i++)
#pragma unroll
        for (int j = 0; j < 4; j++) acc[i][j] = 0.f;
#pragma unroll 8
    for (int k = 0; k < 64; k++) {
        float4 w4 = *(const float4*)&ws[k][tq << 2];
        float wa[4] = {w4.x, w4.y, w4.z, w4.w};
#pragma unroll
        for (int i = 0; i < 4; i++) {
            float v = vs[ts * 4 + i][k];
#pragma unroll
            for (int j = 0; j < 4; j++) acc[i][j] += v * wa[j];
        }
    }
#pragma unroll
    for (int i = 0; i < 4; i++) {
        float4 o = make_float4(acc[i][0], acc[i][1], acc[i][2], acc[i][3]);
        *(float4*)(g_attn + (size_t)(b * SS + s0 + ts * 4 + i) * DD + h * 64 + (tq << 2)) = o;
    }
}

// ---------------- rmsnorm: out[row] = in[row] * rsqrt(mean(in^2)+eps) * g ----------------
__global__ __launch_bounds__(256) void rmsnorm_kernel(const float* __restrict__ in,
                                                      const float* __restrict__ gg,
                                                      float* __restrict__ out) {
    __shared__ float red[8];
    const size_t row = blockIdx.x;
    const int tid = threadIdx.x;
    float4 v = *(const float4*)(in + row * DD + tid * 4);
    float ss = v.x * v.x + v.y * v.y + v.z * v.z + v.w * v.w;
#pragma unroll
    for (int o = 16; o > 0; o >>= 1) ss += __shfl_xor_sync(0xffffffff, ss, o);
    if ((tid & 31) == 0) red[tid >> 5] = ss;
    __syncthreads();
    if (tid < 32) {
        float t = (tid < 8) ? red[tid] : 0.f;
#pragma unroll
        for (int o = 4; o > 0; o >>= 1) t += __shfl_xor_sync(0xffffffff, t, o);
        if (tid == 0) red[0] = t;
    }
    __syncthreads();
    float rs = rsqrtf(red[0] * (1.f / DD) + 1e-6f);
    float4 gv = *(const float4*)(gg + tid * 4);
    float4 o = make_float4(v.x * rs * gv.x, v.y * rs * gv.y, v.z * rs * gv.z, v.w * rs * gv.w);
    *(float4*)(out + row * DD + tid * 4) = o;
}

// ---------------- host ----------------
extern "C" void kernel_launch(void* const* d_in, const int* in_sizes, int n_in,
                              void* d_out, int out_size) {
    const float* x = (const float*)d_in[0];
    const int* amask = (const int*)d_in[1];
    const float* Wq = (const float*)d_in[2];
    const float* bq = (const float*)d_in[3];
    const float* Wk = (const float*)d_in[4];
    const float* bk = (const float*)d_in[5];
    const float* Wv = (const float*)d_in[6];
    const float* bv = (const float*)d_in[7];
    const float* Wo = (const float*)d_in[8];
    const float* bo = (const float*)d_in[9];
    const float* W1 = (const float*)d_in[10];
    const float* b1 = (const float*)d_in[11];
    const float* W2 = (const float*)d_in[12];
    const float* b2 = (const float*)d_in[13];
    const float* g1 = (const float*)d_in[14];
    const float* g2 = (const float*)d_in[15];
    float* out = (float*)d_out;

    float *wqkv, *bqkv, *qkv, *attn, *hbuf, *tbuf;
    cudaGetSymbolAddress((void**)&wqkv, g_wqkv);
    cudaGetSymbolAddress((void**)&bqkv, g_bqkv);
    cudaGetSymbolAddress((void**)&qkv, g_qkv);
    cudaGetSymbolAddress((void**)&attn, g_attn);
    cudaGetSymbolAddress((void**)&hbuf, g_h);
    cudaGetSymbolAddress((void**)&tbuf, g_t);

    // 1. pack weights
    pack_qkv_kernel<<<(DD * N3 + 255) / 256, 256>>>(Wq, Wk, Wv, bq, bk, bv);
    // 2. qkv = x @ Wqkv + b   [32768 x 3072]
    gemm_tf32<0><<<dim3(N3 / 128, MM / 128), 256>>>(x, DD, wqkv, N3, bqkv, nullptr, 0, qkv, N3, DD);
    // 3. score partials + softmax
    scores_kernel<<<dim3(128, 8), 256>>>();
    softmax_kernel<<<128, 64>>>(amask);
    // 4. attn = v @ w
    attn_kernel<<<dim3(128, 64), 256>>>();
    // 5. h = x + attn @ Wo + bo
    gemm_tf32<1><<<dim3(DD / 128, MM / 128), 256>>>(attn, DD, Wo, DD, bo, x, DD, hbuf, DD, DD);
    // 6. h = rmsnorm(h, g1) in place
    rmsnorm_kernel<<<MM, 256>>>(hbuf, g1, hbuf);
    // 7. t = tanh(h @ W1 + b1)
    gemm_tf32<2><<<dim3(FF / 128, MM / 128), 256>>>(hbuf, DD, W1, FF, b1, nullptr, 0, tbuf, FF, DD);
    // 8. h2 = h + t @ W2 + b2   (reuse g_attn)
    gemm_tf32<1><<<dim3(DD / 128, MM / 128), 256>>>(tbuf, FF, W2, DD, b2, hbuf, DD, attn, DD, FF);
    // 9. out = rmsnorm(h2, g2)
    rmsnorm_kernel<<<MM, 256>>>(attn, g2, out);
}

// round 16
// speedup vs baseline: 1.6305x; 1.2449x over previous
#include <cuda_runtime.h>
#include <cuda_fp16.h>
#include <cstdint>
#include <math.h>

// problem constants
#define BB 8
#define SS 4096
#define DD 1024
#define HH 16
#define HD 64
#define FF 128
#define MM (BB * SS)      // 32768
#define N3 (3 * DD)       // 3072

// ---------------- scratch (device globals; runtime alloc forbidden) ----------------
__device__ __align__(256) float g_wqkv[(size_t)N3 * DD];           // packed TRANSPOSED [3072][1024]
__device__ __align__(256) float g_bqkv[N3];
__device__ __align__(256) float g_woT[(size_t)DD * DD];            // Wo^T [1024][1024]
__device__ __align__(256) float g_w1T[(size_t)FF * DD];            // W1^T [128][1024]
__device__ __align__(256) float g_w2T[(size_t)DD * FF];            // W2^T [1024][128]
__device__ __align__(256) float g_qkv[(size_t)MM * N3];            // q|k|v cols: t*1024+h*64+e
__device__ __align__(256) float g_part[(size_t)8 * 128 * HD * HD]; // split-K score partials
__device__ __align__(256) float g_w[(size_t)128 * HD * HD];        // softmax weights [bh][k][q]
__device__ __align__(256) float g_attn[(size_t)MM * DD];           // attn out, later reused as h2
__device__ __align__(256) float g_h[(size_t)MM * DD];              // h (rmsnorm'd in place)
__device__ __align__(256) float g_t[(size_t)MM * FF];              // tanh hidden

// ---------------- helpers ----------------
__device__ __forceinline__ uint32_t f2h2(float x, float y) {
    __half2 h = __floats2half2_rn(x, y);  // x -> low half (first k), y -> high
    return *reinterpret_cast<uint32_t*>(&h);
}
// mma.sync m16n8k16 f16 inputs, f32 accum
__device__ __forceinline__ void mma16(float* c, const uint32_t* a, const uint32_t* b) {
    asm("mma.sync.aligned.m16n8k16.row.col.f32.f16.f16.f32 "
        "{%0,%1,%2,%3}, {%4,%5,%6,%7}, {%8,%9}, {%0,%1,%2,%3};"
        : "+f"(c[0]), "+f"(c[1]), "+f"(c[2]), "+f"(c[3])
        : "r"(a[0]), "r"(a[1]), "r"(a[2]), "r"(a[3]), "r"(b[0]), "r"(b[1]));
}

// ---------------- pack Wq/Wk/Wv (H,D,HD) -> TRANSPOSED [3072 rows][1024 K] ----------------
__global__ void pack_qkv_kernel(const float* __restrict__ Wq, const float* __restrict__ Wk,
                                const float* __restrict__ Wv, const float* __restrict__ bq,
                                const float* __restrict__ bk, const float* __restrict__ bv) {
    size_t idx = (size_t)blockIdx.x * 256 + threadIdx.x;
    if (idx >= (size_t)N3 * DD) return;
    int c = (int)(idx / DD), d = (int)(idx % DD);
    int t = c >> 10, hc = c & 1023;
    const float* W = (t == 0) ? Wq : ((t == 1) ? Wk : Wv);
    g_wqkv[idx] = W[(((size_t)(hc >> 6)) * DD + d) * HD + (hc & 63)];
    if (idx < (size_t)N3) {
        int tb = (int)(idx >> 10), hcb = (int)(idx & 1023);
        const float* bb2 = (tb == 0) ? bq : ((tb == 1) ? bk : bv);
        g_bqkv[idx] = bb2[hcb];
    }
}

// ---------------- tiled transpose: src[R][Ccols] -> dst[Ccols][R] ----------------
__global__ void transpose_kernel(const float* __restrict__ src, float* __restrict__ dst,
                                 int R, int Ccols) {
    __shared__ float t[32][33];
    int bx = blockIdx.x * 32, by = blockIdx.y * 32;
    int tx = threadIdx.x, ty = threadIdx.y;  // (32, 8)
#pragma unroll
    for (int i = 0; i < 32; i += 8) {
        int r = by + ty + i, c = bx + tx;
        if (r < R && c < Ccols) t[ty + i][tx] = src[(size_t)r * Ccols + c];
    }
    __syncthreads();
#pragma unroll
    for (int i = 0; i < 32; i += 8) {
        int r = bx + ty + i, c = by + tx;
        if (r < Ccols && c < R) dst[(size_t)r * R + c] = t[tx][ty + i];
    }
}

// ---------------- fp16 GEMM: C = A(MxK) @ BT(NxK)^T + bias [+res] [tanh] ----------------
// EPI 0: +bias   EPI 1: +bias+res   EPI 2: tanh(.+bias)
// BM=128 BN=128 BK=32, 256 threads (8 warps 4m x 2n), warp tile 32x64, m16n8k16 f16 mma.
// Both operands staged in smem as half2 pairs along K, stride 20 u32 (conflict-free frags).
// Double-buffered, ONE barrier per k-tile, register prefetch of next tile.
template <int EPI>
__global__ __launch_bounds__(256) void gemm_fp16(
    const float* __restrict__ A, int lda,
    const float* __restrict__ BT, int ldb,  // BT: [N][K] row-major, ldb = K
    const float* __restrict__ bias,
    const float* __restrict__ res, int ldr,
    float* __restrict__ C, int ldc, int K) {
    __shared__ __align__(16) uint32_t As[2][128][20];  // 16 used (BK/2 half2), pad->20
    __shared__ __align__(16) uint32_t Bs[2][128][20];

    const int row0 = blockIdx.y * 128, col0 = blockIdx.x * 128;
    const int tid = threadIdx.x, lane = tid & 31, warp = tid >> 5;
    const int wm = warp >> 1, wn = warp & 1;
    const int g = lane >> 2, tg = lane & 3;

    float acc[2][8][4];
#pragma unroll
    for (int i = 0; i < 2; i++)
#pragma unroll
        for (int j = 0; j < 8; j++)
#pragma unroll
            for (int c = 0; c < 4; c++) acc[i][j][c] = 0.f;

    const float* Ab = A + (size_t)row0 * lda;
    const float* Bb = BT + (size_t)col0 * ldb;

    // loader coords: 128 rows x 8 float4 per tile, 4 per thread
    float4 ra[4], rb[4];
#pragma unroll
    for (int p = 0; p < 4; p++) {
        int f = tid + p * 256, r = f >> 3, c4 = f & 7;
        ra[p] = *(const float4*)(Ab + (size_t)r * lda + c4 * 4);
        rb[p] = *(const float4*)(Bb + (size_t)r * ldb + c4 * 4);
    }

    const int ntiles = K >> 5;
    for (int it = 0; it < ntiles; it++) {
        const int buf = it & 1;
#pragma unroll
        for (int p = 0; p < 4; p++) {
            int f = tid + p * 256, r = f >> 3, c4 = f & 7;
            As[buf][r][c4 * 2 + 0] = f2h2(ra[p].x, ra[p].y);
            As[buf][r][c4 * 2 + 1] = f2h2(ra[p].z, ra[p].w);
            Bs[buf][r][c4 * 2 + 0] = f2h2(rb[p].x, rb[p].y);
            Bs[buf][r][c4 * 2 + 1] = f2h2(rb[p].z, rb[p].w);
        }
        __syncthreads();

        if (it + 1 < ntiles) {  // prefetch next tile (overlaps compute)
            const int kt = (it + 1) << 5;
#pragma unroll
            for (int p = 0; p < 4; p++) {
                int f = tid + p * 256, r = f >> 3, c4 = f & 7;
                ra[p] = *(const float4*)(Ab + (size_t)r * lda + kt + c4 * 4);
                rb[p] = *(const float4*)(Bb + (size_t)r * ldb + kt + c4 * 4);
            }
        }

#pragma unroll
        for (int ks = 0; ks < 2; ks++) {  // two k16 steps; half2 base = ks*8
            const int kb = ks * 8;
            uint32_t af[2][4], bf[8][2];
#pragma unroll
            for (int mf = 0; mf < 2; mf++) {
                int m = wm * 32 + mf * 16 + g;
                af[mf][0] = As[buf][m][kb + tg];
                af[mf][1] = As[buf][m + 8][kb + tg];
                af[mf][2] = As[buf][m][kb + tg + 4];
                af[mf][3] = As[buf][m + 8][kb + tg + 4];
            }
#pragma unroll
            for (int nf = 0; nf < 8; nf++) {
                int n = wn * 64 + nf * 8 + g;
                bf[nf][0] = Bs[buf][n][kb + tg];
                bf[nf][1] = Bs[buf][n][kb + tg + 4];
            }
#pragma unroll
            for (int mf = 0; mf < 2; mf++)
#pragma unroll
                for (int nf = 0; nf < 8; nf++) mma16(acc[mf][nf], af[mf], bf[nf]);
        }
        // no second barrier: next store targets the other buffer
    }
    // epilogue: c0=(g,2tg) c1=(g,2tg+1) c2=(g+8,2tg) c3=(g+8,2tg+1); float2 stores
#pragma unroll
    for (int mf = 0; mf < 2; mf++) {
        const int r0 = row0 + wm * 32 + mf * 16 + g;
#pragma unroll
        for (int nf = 0; nf < 8; nf++) {
            const int c = col0 + wn * 64 + nf * 8 + 2 * tg;
            float b0 = bias[c], b1 = bias[c + 1];
            float v0 = acc[mf][nf][0] + b0, v1 = acc[mf][nf][1] + b1;
            float v2 = acc[mf][nf][2] + b0, v3 = acc[mf][nf][3] + b1;
            if (EPI == 1) {
                float2 r_lo = *(const float2*)(res + (size_t)r0 * ldr + c);
                float2 r_hi = *(const float2*)(res + (size_t)(r0 + 8) * ldr + c);
                v0 += r_lo.x; v1 += r_lo.y; v2 += r_hi.x; v3 += r_hi.y;
            }
            if (EPI == 2) { v0 = tanhf(v0); v1 = tanhf(v1); v2 = tanhf(v2); v3 = tanhf(v3); }
            *(float2*)(C + (size_t)r0 * ldc + c) = make_float2(v0, v1);
            *(float2*)(C + (size_t)(r0 + 8) * ldc + c) = make_float2(v2, v3);
        }
    }
}

// ---------------- scores partials: P[k][q] = sum_{s in chunk} K[s,k]*Q[s,q] ----------------
__global__ __launch_bounds__(256) void scores_kernel() {
    __shared__ __align__(16) float Ks[32][68], Qs[32][68];
    const int bh = blockIdx.x, sp = blockIdx.y;
    const int b = bh >> 4, h = bh & 15;
    const int tid = threadIdx.x;
    const int tk = tid >> 4, tq = tid & 15;
    const size_t rowbase = (size_t)(b * SS + sp * 512) * N3;
    const int qoff = h * 64, koff = 1024 + h * 64;

    float acc[4][4];
#pragma unroll
    for (int i = 0; i < 4; i++)
#pragma unroll
        for (int j = 0; j < 4; j++) acc[i][j] = 0.f;

    for (int st = 0; st < 512; st += 32) {
#pragma unroll
        for (int i = 0; i < 2; i++) {
            int L = tid + i * 256;
            int r = L >> 4, c4 = (L & 15) << 2;
            size_t base = rowbase + (size_t)(st + r) * N3;
            *(float4*)&Ks[r][c4] = *(const float4*)(g_qkv + base + koff + c4);
            *(float4*)&Qs[r][c4] = *(const float4*)(g_qkv + base + qoff + c4);
        }
        __syncthreads();
#pragma unroll
        for (int ss = 0; ss < 32; ss++) {
            float4 kk = *(const float4*)&Ks[ss][tk << 2];
            float4 qq = *(const float4*)&Qs[ss][tq << 2];
            float ka[4] = {kk.x, kk.y, kk.z, kk.w};
            float qa[4] = {qq.x, qq.y, qq.z, qq.w};
#pragma unroll
            for (int i = 0; i < 4; i++)
#pragma unroll
                for (int j = 0; j < 4; j++) acc[i][j] += ka[i] * qa[j];
        }
        __syncthreads();
    }
    float* P = g_part + ((size_t)sp * 128 + bh) * 4096;
#pragma unroll
    for (int i = 0; i < 4; i++)
#pragma unroll
        for (int j = 0; j < 4; j++)
            P[(tk * 4 + i) * 64 + (tq * 4 + j)] = acc[i][j];
}

// ---------------- softmax over k: w[k][q] ----------------
__global__ void softmax_kernel(const int* __restrict__ mask) {
    __shared__ float sc[64][65];
    const int bh = blockIdx.x, q = threadIdx.x;  // 64 threads
    const int b = bh >> 4;
    const int mq = mask[b * 64 + q];
    float mx = -3.4e38f;
    for (int k = 0; k < 64; k++) {
        float a = 0.f;
#pragma unroll
        for (int sp = 0; sp < 8; sp++) a += g_part[((size_t)sp * 128 + bh) * 4096 + k * 64 + q];
        a *= 0.125f;
        if (mq == 0) a = -1e30f;
        sc[k][q] = a;
        mx = fmaxf(mx, a);
    }
    float sum = 0.f;
    for (int k = 0; k < 64; k++) {
        float e = __expf(sc[k][q] - mx);
        sc[k][q] = e;
        sum += e;
    }
    float inv = 1.f / sum;
    for (int k = 0; k < 64; k++) g_w[(size_t)bh * 4096 + k * 64 + q] = sc[k][q] * inv;
}

// ---------------- attn: per (bh, s-tile 64): out[s][q] = sum_k v[s][k]*w[k][q] ----------------
__global__ __launch_bounds__(256) void attn_kernel() {
    __shared__ __align__(16) float ws[64][68];
    __shared__ __align__(16) float vs[64][68];
    const int bh = blockIdx.x, stile = blockIdx.y;
    const int b = bh >> 4, h = bh & 15;
    const int tid = threadIdx.x;
    const int s0 = stile * 64;
    const int vbase = 2048 + h * 64;

    for (int i = tid; i < 4096; i += 256) ws[i >> 6][i & 63] = g_w[(size_t)bh * 4096 + i];
#pragma unroll
    for (int i = 0; i < 4; i++) {
        int L = tid + i * 256;
        int r = L >> 4, c4 = (L & 15) << 2;
        *(float4*)&vs[r][c4] =
            *(const float4*)(g_qkv + (size_t)(b * SS + s0 + r) * N3 + vbase + c4);
    }
    __syncthreads();

    const int ts = tid >> 4, tq = tid & 15;
    float acc[4][4];
#pragma unroll
    for (int i = 0; i < 4; i++)
#pragma unroll
        for (int j = 0; j < 4; j++) acc[i][j] = 0.f;
#pragma unroll 8
    for (int k = 0; k < 64; k++) {
        float4 w4 = *(const float4*)&ws[k][tq << 2];
        float wa[4] = {w4.x, w4.y, w4.z, w4.w};
#pragma unroll
        for (int i = 0; i < 4; i++) {
            float v = vs[ts * 4 + i][k];
#pragma unroll
            for (int j = 0; j < 4; j++) acc[i][j] += v * wa[j];
        }
    }
#pragma unroll
    for (int i = 0; i < 4; i++) {
        float4 o = make_float4(acc[i][0], acc[i][1], acc[i][2], acc[i][3]);
        *(float4*)(g_attn + (size_t)(b * SS + s0 + ts * 4 + i) * DD + h * 64 + (tq << 2)) = o;
    }
}

// ---------------- rmsnorm ----------------
__global__ __launch_bounds__(256) void rmsnorm_kernel(const float* __restrict__ in,
                                                      const float* __restrict__ gg,
                                                      float* __restrict__ out) {
    __shared__ float red[8];
    const size_t row = blockIdx.x;
    const int tid = threadIdx.x;
    float4 v = *(const float4*)(in + row * DD + tid * 4);
    float ss = v.x * v.x + v.y * v.y + v.z * v.z + v.w * v.w;
#pragma unroll
    for (int o = 16; o > 0; o >>= 1) ss += __shfl_xor_sync(0xffffffff, ss, o);
    if ((tid & 31) == 0) red[tid >> 5] = ss;
    __syncthreads();
    if (tid < 32) {
        float t = (tid < 8) ? red[tid] : 0.f;
#pragma unroll
        for (int o = 4; o > 0; o >>= 1) t += __shfl_xor_sync(0xffffffff, t, o);
        if (tid == 0) red[0] = t;
    }
    __syncthreads();
    float rs = rsqrtf(red[0] * (1.f / DD) + 1e-6f);
    float4 gv = *(const float4*)(gg + tid * 4);
    float4 o = make_float4(v.x * rs * gv.x, v.y * rs * gv.y, v.z * rs * gv.z, v.w * rs * gv.w);
    *(float4*)(out + row * DD + tid * 4) = o;
}

// ---------------- host ----------------
extern "C" void kernel_launch(void* const* d_in, const int* in_sizes, int n_in,
                              void* d_out, int out_size) {
    const float* x = (const float*)d_in[0];
    const int* amask = (const int*)d_in[1];
    const float* Wq = (const float*)d_in[2];
    const float* bq = (const float*)d_in[3];
    const float* Wk = (const float*)d_in[4];
    const float* bk = (const float*)d_in[5];
    const float* Wv = (const float*)d_in[6];
    const float* bv = (const float*)d_in[7];
    const float* Wo = (const float*)d_in[8];
    const float* bo = (const float*)d_in[9];
    const float* W1 = (const float*)d_in[10];
    const float* b1 = (const float*)d_in[11];
    const float* W2 = (const float*)d_in[12];
    const float* b2 = (const float*)d_in[13];
    const float* g1 = (const float*)d_in[14];
    const float* g2 = (const float*)d_in[15];
    float* out = (float*)d_out;

    float *wqkv, *bqkv, *woT, *w1T, *w2T, *qkv, *attn, *hbuf, *tbuf;
    cudaGetSymbolAddress((void**)&wqkv, g_wqkv);
    cudaGetSymbolAddress((void**)&bqkv, g_bqkv);
    cudaGetSymbolAddress((void**)&woT, g_woT);
    cudaGetSymbolAddress((void**)&w1T, g_w1T);
    cudaGetSymbolAddress((void**)&w2T, g_w2T);
    cudaGetSymbolAddress((void**)&qkv, g_qkv);
    cudaGetSymbolAddress((void**)&attn, g_attn);
    cudaGetSymbolAddress((void**)&hbuf, g_h);
    cudaGetSymbolAddress((void**)&tbuf, g_t);

    dim3 tb(32, 8);
    // 1. pack + transpose weights
    pack_qkv_kernel<<<(N3 * DD + 255) / 256, 256>>>(Wq, Wk, Wv, bq, bk, bv);
    transpose_kernel<<<dim3(DD / 32, DD / 32), tb>>>(Wo, woT, DD, DD);
    transpose_kernel<<<dim3(FF / 32, DD / 32), tb>>>(W1, w1T, DD, FF);
    transpose_kernel<<<dim3(DD / 32, FF / 32), tb>>>(W2, w2T, FF, DD);
    // 2. qkv = x @ Wqkv + b
    gemm_fp16<0><<<dim3(N3 / 128, MM / 128), 256>>>(x, DD, wqkv, DD, bqkv, nullptr, 0, qkv, N3, DD);
    // 3. score partials + softmax
    scores_kernel<<<dim3(128, 8), 256>>>();
    softmax_kernel<<<128, 64>>>(amask);
    // 4. attn = v @ w
    attn_kernel<<<dim3(128, 64), 256>>>();
    // 5. h = x + attn @ Wo + bo
    gemm_fp16<1><<<dim3(DD / 128, MM / 128), 256>>>(attn, DD, woT, DD, bo, x, DD, hbuf, DD, DD);
    // 6. h = rmsnorm(h, g1)
    rmsnorm_kernel<<<MM, 256>>>(hbuf, g1, hbuf);
    // 7. t = tanh(h @ W1 + b1)
    gemm_fp16<2><<<dim3(FF / 128, MM / 128), 256>>>(hbuf, DD, w1T, DD, b1, nullptr, 0, tbuf, FF, DD);
    // 8. h2 = h + t @ W2 + b2
    gemm_fp16<1><<<dim3(DD / 128, MM / 128), 256>>>(tbuf, FF, w2T, FF, b2, hbuf, DD, attn, DD, FF);
    // 9. out = rmsnorm(h2, g2)
    rmsnorm_kernel<<<MM, 256>>>(attn, g2, out);
}